// round 16
// baseline (speedup 1.0000x reference)
#include <cuda_runtime.h>
#include <cuda_fp16.h>
#include <cstdint>

#define NN 50000
#define DD 512
#define EE 150000

#define BM 64
#define BN 128
#define BK 64
#define SA 72              // smem row stride in fp16 (144B rows -> conflict-free ldmatrix)
#define NIT (DD / BK)      // 8

// Stage layout (bytes): Ah 9216 | Bh 18432
#define ST_BH 9216
#define STAGE 27648
#define SMEM_DYN (2 * STAGE)   // 55296 per CTA; 2 CTAs/SM = 110592

// ---------------------------------------------------------------------------
// Device globals (no allocation anywhere)
// ---------------------------------------------------------------------------
__device__ __align__(16) __half g_hs[(size_t)NN * DD];    // scaled messages (fp16, 50MB)
__device__ __align__(16) float  g_bufB[(size_t)NN * DD];  // layer-1 aggregate (fp32)
__device__ __align__(16) __half g_W1h[DD * DD];
__device__ __align__(16) __half g_W2h[DD * DD];
__device__ float g_deg[NN];
__device__ float g_dis[NN];
__device__ int   g_is64;

// ---------------------------------------------------------------------------
// PTX helpers (ldmatrix / mma.sync / cp.async are sm_80+, legal on plain sm_103)
// ---------------------------------------------------------------------------
__device__ __forceinline__ uint32_t smem_u32(const void* p) {
    uint32_t a;
    asm("{ .reg .u64 t; cvta.to.shared.u64 t, %1; cvt.u32.u64 %0, t; }"
        : "=r"(a) : "l"(p));
    return a;
}
#define LDM4(d, addr)                                                           \
    asm volatile("ldmatrix.sync.aligned.m8n8.x4.shared.b16 {%0,%1,%2,%3}, [%4];"\
        : "=r"((d)[0]), "=r"((d)[1]), "=r"((d)[2]), "=r"((d)[3]) : "r"(addr))
#define MMA(cc, aa, b0, b1)                                                     \
    asm volatile("mma.sync.aligned.m16n8k16.row.col.f32.f16.f16.f32 "           \
        "{%0,%1,%2,%3}, {%4,%5,%6,%7}, {%8,%9}, {%0,%1,%2,%3};"                 \
        : "+f"((cc)[0]), "+f"((cc)[1]), "+f"((cc)[2]), "+f"((cc)[3])            \
        : "r"((aa)[0]), "r"((aa)[1]), "r"((aa)[2]), "r"((aa)[3]),               \
          "r"(b0), "r"(b1))
#define CPASYNC16(sm, gm)                                                       \
    asm volatile("cp.async.cg.shared.global [%0], [%1], 16;"                    \
                 :: "r"(sm), "l"(gm) : "memory")
#define CPCOMMIT()  asm volatile("cp.async.commit_group;" ::: "memory")
#define CPWAIT0()   asm volatile("cp.async.wait_group 0;" ::: "memory")

__device__ __forceinline__ uint32_t pack_h2(float a, float b) {
    __half2 t = __floats2half2_rn(a, b);        // x = low half
    return *reinterpret_cast<uint32_t*>(&t);
}
__device__ __forceinline__ int load_idx(const void* __restrict__ ei, int pos) {
    if (g_is64) return (int)((const long long*)ei)[pos];
    return ((const int*)ei)[pos];
}

// ---------------------------------------------------------------------------
// k1: dtype detect (block 0) + deg init
// ---------------------------------------------------------------------------
__global__ void k1_detect_initdeg(const unsigned int* __restrict__ w) {
    if (blockIdx.x == 0 && threadIdx.x == 0) {
        int is64 = 1;
        for (int i = 0; i < 128; i++)
            if (w[2 * i + 1] != 0u) { is64 = 0; break; }
        g_is64 = is64;
    }
    int i = blockIdx.x * blockDim.x + threadIdx.x;
    if (i < NN) g_deg[i] = 1.0f;
}

__global__ void k2_count_deg(const void* __restrict__ ei) {
    int e = blockIdx.x * blockDim.x + threadIdx.x;
    if (e < EE) atomicAdd(&g_deg[load_idx(ei, EE + e)], 1.0f);
}

// ---------------------------------------------------------------------------
// k3: calc_dis ([0,196)) + W1 cvt ([196,452)) + W2 cvt ([452,708))
//     Wh[n][k] = fp16(W[k][n])
// ---------------------------------------------------------------------------
__global__ void k3_dis_wsplit(const float* __restrict__ W1,
                              const float* __restrict__ W2)
{
    int b = blockIdx.x;
    int tid = threadIdx.x;
    if (b < 196) {
        int i = b * 256 + tid;
        if (i < NN) g_dis[i] = rsqrtf(g_deg[i]);
        return;
    }
    int layer = (b < 452) ? 1 : 2;
    int t = (layer == 1) ? (b - 196) : (b - 452);
    const float* __restrict__ W = (layer == 1) ? W1 : W2;
    __half* __restrict__ Wh = (layer == 1) ? g_W1h : g_W2h;

    __shared__ float tt[32][33];
    int k0 = (t & 15) * 32, n0 = (t >> 4) * 32;
    int tx = tid & 31, ty = tid >> 5;
    for (int s = 0; s < 4; s++) {
        int j = ty + 8 * s;
        tt[j][tx] = W[(size_t)(k0 + j) * DD + n0 + tx];
    }
    __syncthreads();
    for (int s = 0; s < 4; s++) {
        int j = ty + 8 * s;
        Wh[(size_t)(n0 + j) * DD + k0 + tx] = __float2half_rn(tt[tx][j]);
    }
}

// ---------------------------------------------------------------------------
// fp16 GEMM: CTA 64x128, 8 warps (2m x 4n), warp tile 32x32, BK=64,
// 2 CTAs/SM, double-buffered smem + double-buffered ldmatrix fragments.
//   h = op(A)@W  with  D = Ah*Bh
// Fused epilogue: g_hs = fp16(h*dis) ; dest = h*dis^2 + bias  (fp32)
// ---------------------------------------------------------------------------
template <bool A_BUFB, bool RELU, int LAYER>
__global__ __launch_bounds__(256, 2) void gemm_f16(
    const float* __restrict__ Aext,
    const float* __restrict__ bias, float* __restrict__ dest_ext, int M)
{
    extern __shared__ __align__(16) char smem[];
    const float* __restrict__ A = A_BUFB ? (const float*)g_bufB : Aext;
    const __half* __restrict__ Wh = (LAYER == 1) ? g_W1h : g_W2h;
    float* __restrict__ dest = A_BUFB ? dest_ext : (float*)g_bufB;
    __half* __restrict__ HS = g_hs;

    const uint32_t sb = smem_u32(smem);
    const int tid = threadIdx.x, lane = tid & 31, wid = tid >> 5;
    const int wm = (wid & 1) * 32;       // 2 warps in m
    const int wn = (wid >> 1) * 32;      // 4 warps in n
    const int bm = blockIdx.y * BM;
    const int n0 = blockIdx.x * BN;

    const int a_row = tid >> 4, a_c4 = tid & 15;         // +16 rows per r
    const int b_row = tid >> 3, b_c = tid & 7;           // +32 rows per r

    float4 pa[4];

    auto issue_B = [&](int k0, int st) {
        uint32_t bh = sb + st * STAGE + ST_BH;
#pragma unroll
        for (int r = 0; r < 4; r++) {
            int row = b_row + 32 * r;
            size_t g = (size_t)(n0 + row) * DD + k0 + b_c * 8;
            uint32_t so = (uint32_t)(row * SA + b_c * 8) * 2;
            CPASYNC16(bh + so, (const void*)&Wh[g]);
        }
        CPCOMMIT();
    };
    auto issue_A = [&](int k0) {
#pragma unroll
        for (int r = 0; r < 4; r++) {
            int row = a_row + 16 * r;
            int g = bm + row;
            float4 v = make_float4(0.f, 0.f, 0.f, 0.f);
            if (g < M) v = *(const float4*)&A[(size_t)g * DD + k0 + a_c4 * 4];
            pa[r] = v;
        }
    };
    auto commit_A = [&](int st) {
        uint32_t ah = sb + st * STAGE;
#pragma unroll
        for (int r = 0; r < 4; r++) {
            int row = a_row + 16 * r;
            float4 v = pa[r];
            if (RELU) {
                v.x = fmaxf(v.x, 0.f); v.y = fmaxf(v.y, 0.f);
                v.z = fmaxf(v.z, 0.f); v.w = fmaxf(v.w, 0.f);
            }
            uint32_t so = (uint32_t)(row * SA + a_c4 * 4) * 2;
            asm volatile("st.shared.v2.b32 [%0], {%1,%2};" ::
                "r"(ah + so), "r"(pack_h2(v.x, v.y)), "r"(pack_h2(v.z, v.w))
                : "memory");
        }
    };

    // Fragment double buffers
    uint32_t ahf[2][2][4];                // [buf][mi][reg]
    uint32_t bhf[2][2][4];                // [buf][nj][reg]

    const uint32_t aoff0 = (uint32_t)(((wm + (lane & 15)) * SA
                          + 8 * (lane >> 4)) * 2);
    const uint32_t boff0 = (uint32_t)(((wn + (lane & 7) + 8 * (lane >> 4)) * SA
                          + 8 * ((lane >> 3) & 1)) * 2);

    auto load_frags = [&](int buf, uint32_t stBase, int k0s) {
        uint32_t aB = stBase + aoff0 + (uint32_t)(k0s * 2);
        uint32_t bB = stBase + ST_BH + boff0 + (uint32_t)(k0s * 2);
#pragma unroll
        for (int mi = 0; mi < 2; mi++)
            LDM4(ahf[buf][mi], aB + (uint32_t)(mi * 16 * SA * 2));
#pragma unroll
        for (int nj = 0; nj < 2; nj++)
            LDM4(bhf[buf][nj], bB + (uint32_t)(nj * 16 * SA * 2));
    };

    float c[2][4][4];
#pragma unroll
    for (int i = 0; i < 2; i++)
#pragma unroll
        for (int j = 0; j < 4; j++)
#pragma unroll
            for (int q = 0; q < 4; q++) c[i][j][q] = 0.0f;

    auto do_mma = [&](int buf) {
#pragma unroll
        for (int nj = 0; nj < 2; nj++)
#pragma unroll
            for (int mi = 0; mi < 2; mi++) {
                MMA(c[mi][nj * 2],     ahf[buf][mi], bhf[buf][nj][0], bhf[buf][nj][1]);
                MMA(c[mi][nj * 2 + 1], ahf[buf][mi], bhf[buf][nj][2], bhf[buf][nj][3]);
            }
    };

    // Prologue: fill stage 0
    issue_B(0, 0);
    issue_A(0);
    commit_A(0);
    CPWAIT0();
    __syncthreads();

    for (int it = 0; it < NIT; it++) {
        const int st = it & 1;
        const bool more = (it + 1 < NIT);
        if (more) {
            issue_B((it + 1) * BK, st ^ 1);
            issue_A((it + 1) * BK);
        }
        const uint32_t stBase = sb + st * STAGE;

        load_frags(0, stBase, 0);
#pragma unroll
        for (int ks = 0; ks < 4; ks++) {
            if (ks < 3) load_frags((ks + 1) & 1, stBase, (ks + 1) * 16);
            do_mma(ks & 1);
        }

        if (more) {
            commit_A(st ^ 1);
            CPWAIT0();
        }
        __syncthreads();
    }

    // Fused epilogue: g_hs = fp16(h*dis), dest = h*dis^2 + bias (fp32)
#pragma unroll
    for (int mi = 0; mi < 2; mi++) {
        int r0 = bm + wm + mi * 16 + (lane >> 2);
        int r1 = r0 + 8;
        float d0 = (r0 < M) ? g_dis[r0] : 0.f;
        float d1 = (r1 < M) ? g_dis[r1] : 0.f;
#pragma unroll
        for (int nj2 = 0; nj2 < 4; nj2++) {
            int col = n0 + wn + nj2 * 8 + (lane & 3) * 2;
            float2 bv = *(const float2*)&bias[col];
            if (r0 < M) {
                float h0 = c[mi][nj2][0] * d0, h1 = c[mi][nj2][1] * d0;
                *(uint32_t*)&HS[(size_t)r0 * DD + col] = pack_h2(h0, h1);
                *(float2*)&dest[(size_t)r0 * DD + col] =
                    make_float2(fmaf(h0, d0, bv.x), fmaf(h1, d0, bv.y));
            }
            if (r1 < M) {
                float h0 = c[mi][nj2][2] * d1, h1 = c[mi][nj2][3] * d1;
                *(uint32_t*)&HS[(size_t)r1 * DD + col] = pack_h2(h0, h1);
                *(float2*)&dest[(size_t)r1 * DD + col] =
                    make_float2(fmaf(h0, d1, bv.x), fmaf(h1, d1, bv.y));
            }
        }
    }
}

// ---------------------------------------------------------------------------
// Edge scatter: agg[dst,:] += dis[dst] * fp16->fp32(hs[src,:])
// One warp per edge; hs row = 1KB (fp16), RED in fp32.
// ---------------------------------------------------------------------------
template <bool TO_BUFB>
__global__ __launch_bounds__(256) void edge_scatter_kernel(
    const void* __restrict__ ei, float* __restrict__ agg_ext)
{
    float* __restrict__ agg = TO_BUFB ? (float*)g_bufB : agg_ext;
    const __half* __restrict__ hs = g_hs;
    int warp = (blockIdx.x * blockDim.x + threadIdx.x) >> 5;
    int lane = threadIdx.x & 31;
    if (warp >= EE) return;
    int s = load_idx(ei, warp);
    int d = load_idx(ei, EE + warp);
    float w = g_dis[d];
    const uint4* hr = (const uint4*)(hs + (size_t)s * DD);   // 64 x uint4
    float* ar = agg + (size_t)d * DD;
#pragma unroll
    for (int i = 0; i < 2; i++) {
        int j = lane + i * 32;              // uint4 index: covers cols 8j..8j+7
        uint4 v = hr[j];
        float2 f0 = __half22float2(*(__half2*)&v.x);
        float2 f1 = __half22float2(*(__half2*)&v.y);
        float2 f2 = __half22float2(*(__half2*)&v.z);
        float2 f3 = __half22float2(*(__half2*)&v.w);
        float* p = ar + j * 8;
        asm volatile("red.global.add.v4.f32 [%0], {%1,%2,%3,%4};"
                     :: "l"(p), "f"(f0.x * w), "f"(f0.y * w),
                        "f"(f1.x * w), "f"(f1.y * w) : "memory");
        asm volatile("red.global.add.v4.f32 [%0], {%1,%2,%3,%4};"
                     :: "l"(p + 4), "f"(f2.x * w), "f"(f2.y * w),
                        "f"(f3.x * w), "f"(f3.y * w) : "memory");
    }
}

// ---------------------------------------------------------------------------
// >48KB dynamic smem opt-in (non-stream API: capture-safe; also at static init)
// ---------------------------------------------------------------------------
static void set_smem_attrs() {
    cudaFuncSetAttribute(gemm_f16<false, false, 1>,
                         cudaFuncAttributeMaxDynamicSharedMemorySize, SMEM_DYN);
    cudaFuncSetAttribute(gemm_f16<true, true, 2>,
                         cudaFuncAttributeMaxDynamicSharedMemorySize, SMEM_DYN);
}
namespace { struct GInit { GInit() { set_smem_attrs(); } } g_init; }

// ---------------------------------------------------------------------------
// Launch (graph-capturable; launch #4 = gemm1 for ncu's profiled slot)
// ---------------------------------------------------------------------------
extern "C" void kernel_launch(void* const* d_in, const int* in_sizes, int n_in,
                              void* d_out, int out_size)
{
    const float* x  = (const float*)d_in[0];
    const void*  ei = d_in[1];
    const float* W1 = (const float*)d_in[2];
    const float* b1 = (const float*)d_in[3];
    const float* W2 = (const float*)d_in[4];
    const float* b2 = (const float*)d_in[5];
    float* out = (float*)d_out;

    set_smem_attrs();

    dim3 gemm_grid(DD / BN, (NN + BM - 1) / BM);   // (4, 782); x-major: same-bm adjacent
    const int edge_blocks = (EE + 7) / 8;

    k1_detect_initdeg<<<196, 256>>>((const unsigned int*)ei);              // #1
    k2_count_deg<<<(EE + 255) / 256, 256>>>(ei);                           // #2
    k3_dis_wsplit<<<708, 256>>>(W1, W2);                                   // #3

    gemm_f16<false, false, 1><<<gemm_grid, 256, SMEM_DYN>>>(x, b1, nullptr, NN); // #4
    edge_scatter_kernel<true><<<edge_blocks, 256>>>(ei, nullptr);                // #5

    gemm_f16<true, true, 2><<<gemm_grid, 256, SMEM_DYN>>>(nullptr, b2, out, NN); // #6
    edge_scatter_kernel<false><<<edge_blocks, 256>>>(ei, out);                   // #7
}

// round 17
// speedup vs baseline: 1.1720x; 1.1720x over previous
#include <cuda_runtime.h>
#include <cuda_fp16.h>
#include <cstdint>

#define NN 50000
#define DD 512
#define EE 150000

#define BM 64
#define BN 128
#define BK 64
#define SA 72              // smem row stride in fp16 (144B rows -> conflict-free ldmatrix)
#define NIT (DD / BK)      // 8

// Stage layout (bytes): Ah 9216 | Bh 18432
#define ST_BH 9216
#define STAGE 27648
#define SMEM_DYN (2 * STAGE)   // 55296 per CTA; 2 CTAs/SM

// ---------------------------------------------------------------------------
// Device globals (no allocation anywhere)
// ---------------------------------------------------------------------------
__device__ __align__(16) __half g_hs[(size_t)NN * DD];    // scaled messages (fp16, 50MB)
__device__ __align__(16) float  g_bufB[(size_t)NN * DD];  // layer-1 aggregate (fp32)
__device__ __align__(16) __half g_W1h[DD * DD];
__device__ __align__(16) __half g_W2h[DD * DD];
__device__ float g_deg[NN];
__device__ float g_dis[NN];
__device__ int   g_off[NN];        // CSR row offsets (by dst)
__device__ int   g_elist[EE];      // src indices bucketed by dst
__device__ int   g_cursor[NN];
__device__ int   g_is64;

// ---------------------------------------------------------------------------
// PTX helpers (ldmatrix / mma.sync / cp.async are sm_80+, legal on plain sm_103)
// ---------------------------------------------------------------------------
__device__ __forceinline__ uint32_t smem_u32(const void* p) {
    uint32_t a;
    asm("{ .reg .u64 t; cvta.to.shared.u64 t, %1; cvt.u32.u64 %0, t; }"
        : "=r"(a) : "l"(p));
    return a;
}
#define LDM4(d, addr)                                                           \
    asm volatile("ldmatrix.sync.aligned.m8n8.x4.shared.b16 {%0,%1,%2,%3}, [%4];"\
        : "=r"((d)[0]), "=r"((d)[1]), "=r"((d)[2]), "=r"((d)[3]) : "r"(addr))
#define MMA(cc, aa, b0, b1)                                                     \
    asm volatile("mma.sync.aligned.m16n8k16.row.col.f32.f16.f16.f32 "           \
        "{%0,%1,%2,%3}, {%4,%5,%6,%7}, {%8,%9}, {%0,%1,%2,%3};"                 \
        : "+f"((cc)[0]), "+f"((cc)[1]), "+f"((cc)[2]), "+f"((cc)[3])            \
        : "r"((aa)[0]), "r"((aa)[1]), "r"((aa)[2]), "r"((aa)[3]),               \
          "r"(b0), "r"(b1))
#define CPASYNC16(sm, gm)                                                       \
    asm volatile("cp.async.cg.shared.global [%0], [%1], 16;"                    \
                 :: "r"(sm), "l"(gm) : "memory")
#define CPCOMMIT()  asm volatile("cp.async.commit_group;" ::: "memory")
#define CPWAIT0()   asm volatile("cp.async.wait_group 0;" ::: "memory")

__device__ __forceinline__ uint32_t pack_h2(float a, float b) {
    __half2 t = __floats2half2_rn(a, b);        // x = low half
    return *reinterpret_cast<uint32_t*>(&t);
}
__device__ __forceinline__ int load_idx(const void* __restrict__ ei, int pos) {
    if (g_is64) return (int)((const long long*)ei)[pos];
    return ((const int*)ei)[pos];
}

// ---------------------------------------------------------------------------
// k1: dtype detect (block 0) + deg init + cursor zero
// ---------------------------------------------------------------------------
__global__ void k1_detect_initdeg(const unsigned int* __restrict__ w) {
    if (blockIdx.x == 0 && threadIdx.x == 0) {
        int is64 = 1;
        for (int i = 0; i < 128; i++)
            if (w[2 * i + 1] != 0u) { is64 = 0; break; }
        g_is64 = is64;
    }
    int i = blockIdx.x * blockDim.x + threadIdx.x;
    if (i < NN) { g_deg[i] = 1.0f; g_cursor[i] = 0; }
}

__global__ void k2_count_deg(const void* __restrict__ ei) {
    int e = blockIdx.x * blockDim.x + threadIdx.x;
    if (e < EE) atomicAdd(&g_deg[load_idx(ei, EE + e)], 1.0f);
}

// ---------------------------------------------------------------------------
// k3: calc_dis ([0,196)) + W1 cvt ([196,452)) + W2 cvt ([452,708))
//     + CSR offset scan (block 708; counts = deg-1, exclusive scan)
// ---------------------------------------------------------------------------
__global__ void k3_dis_wsplit(const float* __restrict__ W1,
                              const float* __restrict__ W2)
{
    int b = blockIdx.x;
    int tid = threadIdx.x;
    if (b < 196) {
        int i = b * 256 + tid;
        if (i < NN) g_dis[i] = rsqrtf(g_deg[i]);
        return;
    }
    if (b == 708) {
        // Two-pass exclusive scan of (deg[i]-1), thread-sequential ranges
        __shared__ int part[256];
        const int R = (NN + 255) / 256;       // 196
        int lo = tid * R, hi = min(lo + R, NN);
        int s = 0;
        for (int i = lo; i < hi; i++) s += (int)g_deg[i] - 1;
        part[tid] = s;
        __syncthreads();
        // exclusive scan of 256 partials (simple smem scan)
        for (int st = 1; st < 256; st <<= 1) {
            int t = (tid >= st) ? part[tid - st] : 0;
            __syncthreads();
            part[tid] += t;
            __syncthreads();
        }
        int run = part[tid] - s;              // exclusive prefix
        for (int i = lo; i < hi; i++) {
            g_off[i] = run;
            run += (int)g_deg[i] - 1;
        }
        return;
    }
    int layer = (b < 452) ? 1 : 2;
    int t = (layer == 1) ? (b - 196) : (b - 452);
    const float* __restrict__ W = (layer == 1) ? W1 : W2;
    __half* __restrict__ Wh = (layer == 1) ? g_W1h : g_W2h;

    __shared__ float tt[32][33];
    int k0 = (t & 15) * 32, n0 = (t >> 4) * 32;
    int tx = tid & 31, ty = tid >> 5;
    for (int s = 0; s < 4; s++) {
        int j = ty + 8 * s;
        tt[j][tx] = W[(size_t)(k0 + j) * DD + n0 + tx];
    }
    __syncthreads();
    for (int s = 0; s < 4; s++) {
        int j = ty + 8 * s;
        Wh[(size_t)(n0 + j) * DD + k0 + tx] = __float2half_rn(tt[tx][j]);
    }
}

// k4: bucket-fill edge lists (order nondeterministic; sums stay within tol)
__global__ void k4_fill(const void* __restrict__ ei) {
    int e = blockIdx.x * blockDim.x + threadIdx.x;
    if (e >= EE) return;
    int s = load_idx(ei, e);
    int d = load_idx(ei, EE + e);
    int pos = atomicAdd(&g_cursor[d], 1);
    g_elist[g_off[d] + pos] = s;
}

// ---------------------------------------------------------------------------
// fp16 GEMM: CTA 64x128, 8 warps (2m x 4n), warp tile 32x32, BK=64,
// 2 CTAs/SM, double-buffered smem + double-buffered ldmatrix fragments.
//   h = op(A)@W ; epilogue writes ONLY g_hs = fp16(h*dis)
// ---------------------------------------------------------------------------
template <bool A_BUFB, bool RELU, int LAYER>
__global__ __launch_bounds__(256, 2) void gemm_f16(
    const float* __restrict__ Aext, int M)
{
    extern __shared__ __align__(16) char smem[];
    const float* __restrict__ A = A_BUFB ? (const float*)g_bufB : Aext;
    const __half* __restrict__ Wh = (LAYER == 1) ? g_W1h : g_W2h;
    __half* __restrict__ HS = g_hs;

    const uint32_t sb = smem_u32(smem);
    const int tid = threadIdx.x, lane = tid & 31, wid = tid >> 5;
    const int wm = (wid & 1) * 32;
    const int wn = (wid >> 1) * 32;
    const int bm = blockIdx.y * BM;
    const int n0 = blockIdx.x * BN;

    const int a_row = tid >> 4, a_c4 = tid & 15;
    const int b_row = tid >> 3, b_c = tid & 7;

    float4 pa[4];

    auto issue_B = [&](int k0, int st) {
        uint32_t bh = sb + st * STAGE + ST_BH;
#pragma unroll
        for (int r = 0; r < 4; r++) {
            int row = b_row + 32 * r;
            size_t g = (size_t)(n0 + row) * DD + k0 + b_c * 8;
            uint32_t so = (uint32_t)(row * SA + b_c * 8) * 2;
            CPASYNC16(bh + so, (const void*)&Wh[g]);
        }
        CPCOMMIT();
    };
    auto issue_A = [&](int k0) {
#pragma unroll
        for (int r = 0; r < 4; r++) {
            int row = a_row + 16 * r;
            int g = bm + row;
            float4 v = make_float4(0.f, 0.f, 0.f, 0.f);
            if (g < M) v = *(const float4*)&A[(size_t)g * DD + k0 + a_c4 * 4];
            pa[r] = v;
        }
    };
    auto commit_A = [&](int st) {
        uint32_t ah = sb + st * STAGE;
#pragma unroll
        for (int r = 0; r < 4; r++) {
            int row = a_row + 16 * r;
            float4 v = pa[r];
            if (RELU) {
                v.x = fmaxf(v.x, 0.f); v.y = fmaxf(v.y, 0.f);
                v.z = fmaxf(v.z, 0.f); v.w = fmaxf(v.w, 0.f);
            }
            uint32_t so = (uint32_t)(row * SA + a_c4 * 4) * 2;
            asm volatile("st.shared.v2.b32 [%0], {%1,%2};" ::
                "r"(ah + so), "r"(pack_h2(v.x, v.y)), "r"(pack_h2(v.z, v.w))
                : "memory");
        }
    };

    uint32_t ahf[2][2][4];
    uint32_t bhf[2][2][4];

    const uint32_t aoff0 = (uint32_t)(((wm + (lane & 15)) * SA
                          + 8 * (lane >> 4)) * 2);
    const uint32_t boff0 = (uint32_t)(((wn + (lane & 7) + 8 * (lane >> 4)) * SA
                          + 8 * ((lane >> 3) & 1)) * 2);

    auto load_frags = [&](int buf, uint32_t stBase, int k0s) {
        uint32_t aB = stBase + aoff0 + (uint32_t)(k0s * 2);
        uint32_t bB = stBase + ST_BH + boff0 + (uint32_t)(k0s * 2);
#pragma unroll
        for (int mi = 0; mi < 2; mi++)
            LDM4(ahf[buf][mi], aB + (uint32_t)(mi * 16 * SA * 2));
#pragma unroll
        for (int nj = 0; nj < 2; nj++)
            LDM4(bhf[buf][nj], bB + (uint32_t)(nj * 16 * SA * 2));
    };

    float c[2][4][4];
#pragma unroll
    for (int i = 0; i < 2; i++)
#pragma unroll
        for (int j = 0; j < 4; j++)
#pragma unroll
            for (int q = 0; q < 4; q++) c[i][j][q] = 0.0f;

    auto do_mma = [&](int buf) {
#pragma unroll
        for (int nj = 0; nj < 2; nj++)
#pragma unroll
            for (int mi = 0; mi < 2; mi++) {
                MMA(c[mi][nj * 2],     ahf[buf][mi], bhf[buf][nj][0], bhf[buf][nj][1]);
                MMA(c[mi][nj * 2 + 1], ahf[buf][mi], bhf[buf][nj][2], bhf[buf][nj][3]);
            }
    };

    issue_B(0, 0);
    issue_A(0);
    commit_A(0);
    CPWAIT0();
    __syncthreads();

    for (int it = 0; it < NIT; it++) {
        const int st = it & 1;
        const bool more = (it + 1 < NIT);
        if (more) {
            issue_B((it + 1) * BK, st ^ 1);
            issue_A((it + 1) * BK);
        }
        const uint32_t stBase = sb + st * STAGE;

        load_frags(0, stBase, 0);
#pragma unroll
        for (int ks = 0; ks < 4; ks++) {
            if (ks < 3) load_frags((ks + 1) & 1, stBase, (ks + 1) * 16);
            do_mma(ks & 1);
        }

        if (more) {
            commit_A(st ^ 1);
            CPWAIT0();
        }
        __syncthreads();
    }

    // Epilogue: write only hs = fp16(h * dis[row])
#pragma unroll
    for (int mi = 0; mi < 2; mi++) {
        int r0 = bm + wm + mi * 16 + (lane >> 2);
        int r1 = r0 + 8;
        float d0 = (r0 < M) ? g_dis[r0] : 0.f;
        float d1 = (r1 < M) ? g_dis[r1] : 0.f;
#pragma unroll
        for (int nj2 = 0; nj2 < 4; nj2++) {
            int col = n0 + wn + nj2 * 8 + (lane & 3) * 2;
            if (r0 < M)
                *(uint32_t*)&HS[(size_t)r0 * DD + col] =
                    pack_h2(c[mi][nj2][0] * d0, c[mi][nj2][1] * d0);
            if (r1 < M)
                *(uint32_t*)&HS[(size_t)r1 * DD + col] =
                    pack_h2(c[mi][nj2][2] * d1, c[mi][nj2][3] * d1);
        }
    }
}

// ---------------------------------------------------------------------------
// CSR gather: one 128-thread CTA per node.
//   dest[i,:] = dis[i] * (hs[i,:] + sum_{src->i} hs[src,:]) + bias
// No atomics; fp32 accumulation; hs rows are fp16 (1KB, L2-resident buffer).
// ---------------------------------------------------------------------------
template <bool TO_BUFB>
__global__ __launch_bounds__(128) void gather_kernel(
    const float* __restrict__ bias, float* __restrict__ dest_ext)
{
    float* __restrict__ dest = TO_BUFB ? (float*)g_bufB : dest_ext;
    const __half* __restrict__ hs = g_hs;
    const int node = blockIdx.x;
    const int tid = threadIdx.x;              // 4 cols per thread (uint2 = 4 halves)

    const uint2* self = (const uint2*)(hs + (size_t)node * DD);
    uint2 v = self[tid];
    float2 f0 = __half22float2(*(__half2*)&v.x);
    float2 f1 = __half22float2(*(__half2*)&v.y);
    float4 acc = make_float4(f0.x, f0.y, f1.x, f1.y);

    const int off = g_off[node];
    const int cnt = (int)g_deg[node] - 1;
    for (int j = 0; j < cnt; j++) {
        int src = g_elist[off + j];           // broadcast load
        uint2 w = ((const uint2*)(hs + (size_t)src * DD))[tid];
        float2 a0 = __half22float2(*(__half2*)&w.x);
        float2 a1 = __half22float2(*(__half2*)&w.y);
        acc.x += a0.x; acc.y += a0.y; acc.z += a1.x; acc.w += a1.y;
    }
    float dis = g_dis[node];
    float4 bv = ((const float4*)bias)[tid];
    float4 o;
    o.x = fmaf(acc.x, dis, bv.x);
    o.y = fmaf(acc.y, dis, bv.y);
    o.z = fmaf(acc.z, dis, bv.z);
    o.w = fmaf(acc.w, dis, bv.w);
    ((float4*)(dest + (size_t)node * DD))[tid] = o;
}

// ---------------------------------------------------------------------------
// >48KB dynamic smem opt-in (non-stream API: capture-safe; also at static init)
// ---------------------------------------------------------------------------
static void set_smem_attrs() {
    cudaFuncSetAttribute(gemm_f16<false, false, 1>,
                         cudaFuncAttributeMaxDynamicSharedMemorySize, SMEM_DYN);
    cudaFuncSetAttribute(gemm_f16<true, true, 2>,
                         cudaFuncAttributeMaxDynamicSharedMemorySize, SMEM_DYN);
}
namespace { struct GInit { GInit() { set_smem_attrs(); } } g_init; }

// ---------------------------------------------------------------------------
// Launch (graph-capturable; launch #4 = gemm1 for ncu's profiled slot)
// ---------------------------------------------------------------------------
extern "C" void kernel_launch(void* const* d_in, const int* in_sizes, int n_in,
                              void* d_out, int out_size)
{
    const float* x  = (const float*)d_in[0];
    const void*  ei = d_in[1];
    const float* W1 = (const float*)d_in[2];
    const float* b1 = (const float*)d_in[3];
    const float* W2 = (const float*)d_in[4];
    const float* b2 = (const float*)d_in[5];
    float* out = (float*)d_out;

    set_smem_attrs();

    dim3 gemm_grid(DD / BN, (NN + BM - 1) / BM);   // (4, 782)

    k1_detect_initdeg<<<196, 256>>>((const unsigned int*)ei);              // #1
    k2_count_deg<<<(EE + 255) / 256, 256>>>(ei);                           // #2
    k3_dis_wsplit<<<709, 256>>>(W1, W2);                                   // #3 (+scan blk)

    gemm_f16<false, false, 1><<<gemm_grid, 256, SMEM_DYN>>>(x, NN);        // #4 (profiled)
    k4_fill<<<(EE + 255) / 256, 256>>>(ei);                                // #5
    gather_kernel<true><<<NN, 128>>>(b1, nullptr);                         // #6

    gemm_f16<true, true, 2><<<gemm_grid, 256, SMEM_DYN>>>(nullptr, NN);    // #7
    gather_kernel<false><<<NN, 128>>>(b2, out);                            // #8
}